// round 1
// baseline (speedup 1.0000x reference)
#include <cuda_runtime.h>
#include <cstdint>
#include <cstddef>

// FusedAGGemm: C[M,N] = sum_r A_r[M,KLOC] @ W[r*KLOC:(r+1)*KLOC, N] + bias
//   all_act : (8, 4096, 1024) fp32  == A_full (4096 x 8192) in shard-major layout
//   local_W : (8192, 1024) fp32
//   bias    : (1024,) fp32
//   out     : (4096, 1024) fp32
//
// SIMT fp32 GEMM baseline using packed fma.rn.f32x2 (FFMA2) to reach the
// 128 FMA/cyc/SM fp32 ceiling. 128x128 block tile, BK=16, 8x8 per thread.

using u64 = unsigned long long;

#define MDIM 4096
#define KLOC 1024
#define KDIM 8192
#define NDIM 1024

#define BM 128
#define BN 128
#define BK 16
#define NTHREADS 256
#define NTILES (KDIM / BK)

__device__ __forceinline__ u64 pack2(float lo, float hi) {
    u64 r;
    asm("mov.b64 %0, {%1, %2};" : "=l"(r) : "f"(lo), "f"(hi));
    return r;
}
__device__ __forceinline__ void unpack2(u64 v, float& lo, float& hi) {
    asm("mov.b64 {%0, %1}, %2;" : "=f"(lo), "=f"(hi) : "l"(v));
}
__device__ __forceinline__ void ffma2(u64& c, u64 a, u64 b) {
    asm("fma.rn.f32x2 %0, %1, %2, %0;" : "+l"(c) : "l"(a), "l"(b));
}

__global__ __launch_bounds__(NTHREADS, 2)
void fused_ag_gemm_kernel(const float* __restrict__ A,
                          const float* __restrict__ W,
                          const float* __restrict__ bias,
                          float* __restrict__ C)
{
    // +4 float pad: keeps rows 16B-aligned (132*4 = 528 = 33*16) and breaks
    // the 4-way STS bank conflict on the transposed A stores.
    __shared__ float As[BK][BM + 4];   // [k][m]
    __shared__ float Bs[BK][BN + 4];   // [k][n]

    const int tid = threadIdx.x;
    const int tx  = tid & 15;   // n-group  (4 cols + 4 cols at +64)
    const int ty  = tid >> 4;   // m-group  (4 rows + 4 rows at +64)
    const int m0  = blockIdx.y * BM;
    const int n0  = blockIdx.x * BN;

    u64 acc[8][4];
    #pragma unroll
    for (int i = 0; i < 8; ++i)
        #pragma unroll
        for (int j = 0; j < 4; ++j) acc[i][j] = 0ull;

    // Global->reg prefetch buffers (2 float4 each for A and B per tile).
    float4 aReg[2], bReg[2];

    // Per-thread load coordinates (constant across tiles).
    int am[2], akg[2], bk[2], bn[2];
    #pragma unroll
    for (int i = 0; i < 2; ++i) {
        int f = tid + i * NTHREADS;       // f in [0, 512)
        am[i]  = f >> 2;                  // m row within tile   (A tile: 128 x 16)
        akg[i] = f & 3;                   // k-group of 4        (float4 along k)
        bk[i]  = f >> 5;                  // k row within tile   (B tile: 16 x 128)
        bn[i]  = f & 31;                  // n-group of 4        (float4 along n)
    }

    auto load_tile = [&](int kt) {
        const int k0 = kt * BK;
        const int r  = k0 >> 10;           // shard index (BK=16 never crosses shards)
        const int kk = k0 & (KLOC - 1);
        const float* Ab = A + (size_t)r * MDIM * KLOC + (size_t)m0 * KLOC + kk;
        #pragma unroll
        for (int i = 0; i < 2; ++i)
            aReg[i] = *reinterpret_cast<const float4*>(
                Ab + (size_t)am[i] * KLOC + akg[i] * 4);
        const float* Wb = W + (size_t)k0 * NDIM + n0;
        #pragma unroll
        for (int i = 0; i < 2; ++i)
            bReg[i] = *reinterpret_cast<const float4*>(
                Wb + (size_t)bk[i] * NDIM + bn[i] * 4);
    };

    load_tile(0);

    for (int kt = 0; kt < NTILES; ++kt) {
        __syncthreads();   // previous tile's compute done -> safe to overwrite smem
        #pragma unroll
        for (int i = 0; i < 2; ++i) {
            As[akg[i] * 4 + 0][am[i]] = aReg[i].x;
            As[akg[i] * 4 + 1][am[i]] = aReg[i].y;
            As[akg[i] * 4 + 2][am[i]] = aReg[i].z;
            As[akg[i] * 4 + 3][am[i]] = aReg[i].w;
            *reinterpret_cast<float4*>(&Bs[bk[i]][bn[i] * 4]) = bReg[i];
        }
        __syncthreads();

        if (kt + 1 < NTILES) load_tile(kt + 1);   // overlap next tile's GMEM latency

        #pragma unroll
        for (int k = 0; k < BK; ++k) {
            float4 a0 = *reinterpret_cast<const float4*>(&As[k][ty * 4]);
            float4 a1 = *reinterpret_cast<const float4*>(&As[k][64 + ty * 4]);
            float4 b0 = *reinterpret_cast<const float4*>(&Bs[k][tx * 4]);
            float4 b1 = *reinterpret_cast<const float4*>(&Bs[k][64 + tx * 4]);

            u64 bp[4] = { pack2(b0.x, b0.y), pack2(b0.z, b0.w),
                          pack2(b1.x, b1.y), pack2(b1.z, b1.w) };
            float av[8] = { a0.x, a0.y, a0.z, a0.w, a1.x, a1.y, a1.z, a1.w };

            #pragma unroll
            for (int i = 0; i < 8; ++i) {
                u64 aa = pack2(av[i], av[i]);
                #pragma unroll
                for (int j = 0; j < 4; ++j) ffma2(acc[i][j], aa, bp[j]);
            }
        }
    }

    // Epilogue: unpack, add bias, vectorized store.
    float4 bias0 = *reinterpret_cast<const float4*>(bias + n0 + tx * 4);
    float4 bias1 = *reinterpret_cast<const float4*>(bias + n0 + 64 + tx * 4);

    #pragma unroll
    for (int i = 0; i < 8; ++i) {
        int m = m0 + ((i < 4) ? (ty * 4 + i) : (64 + ty * 4 + (i - 4)));
        float v[8];
        unpack2(acc[i][0], v[0], v[1]);
        unpack2(acc[i][1], v[2], v[3]);
        unpack2(acc[i][2], v[4], v[5]);
        unpack2(acc[i][3], v[6], v[7]);
        float4 o0 = { v[0] + bias0.x, v[1] + bias0.y, v[2] + bias0.z, v[3] + bias0.w };
        float4 o1 = { v[4] + bias1.x, v[5] + bias1.y, v[6] + bias1.z, v[7] + bias1.w };
        *reinterpret_cast<float4*>(C + (size_t)m * NDIM + n0 + tx * 4) = o0;
        *reinterpret_cast<float4*>(C + (size_t)m * NDIM + n0 + 64 + tx * 4) = o1;
    }
}

extern "C" void kernel_launch(void* const* d_in, const int* in_sizes, int n_in,
                              void* d_out, int out_size)
{
    const float* all_act = (const float*)d_in[0];   // (8, 4096, 1024)
    const float* local_W = (const float*)d_in[1];   // (8192, 1024)
    const float* bias    = (const float*)d_in[2];   // (1024,)
    float* out = (float*)d_out;                     // (4096, 1024)

    dim3 grid(NDIM / BN, MDIM / BM);                // (8, 32) = 256 CTAs
    fused_ag_gemm_kernel<<<grid, NTHREADS>>>(all_act, local_W, bias, out);
}

// round 6
// speedup vs baseline: 2.4851x; 2.4851x over previous
#include <cuda_runtime.h>
#include <cstdint>
#include <cstddef>

// FusedAGGemm via legacy mma.sync tf32 (HMMA) — tcgen05.ld/wait/dealloc are
// rejected by this toolchain's sm_103 (non-'a') ptxas target, so TMEM
// accumulators are unusable. mma.sync.m16n8k8.tf32 + ldmatrix are base-ISA.
//
//   C[M,N] = sum_r A_r[M,KLOC] @ W[r*KLOC:(r+1)*KLOC, N] + bias
// Step 1: transpose W (K,N)->(N,K) into g_Wt so both operands are K-major.
// Step 2: 128x128 CTA tile, BK=32, SW128 smem, ldmatrix.x4 fragment feeds,
//         mma.sync tf32 with fp32 register accumulators.
// Inputs pre-rounded with cvt.rna.tf32 (kills truncation bias).

#define MDIM 4096
#define KLOC 1024
#define KDIM 8192
#define NDIM 1024

#define BM 128
#define BN 128
#define BK 32
#define NTH 256
#define NTILES (KDIM / BK)   // 256

#define SWZ(o) ((o) ^ (((o) >> 3) & 0x70))
#define STAGE_BYTES 32768
#define SM_A(s) ((s) * STAGE_BYTES)
#define SM_B(s) ((s) * STAGE_BYTES + 16384)
#define SMEM_TOTAL (2 * STAGE_BYTES)

__device__ float g_Wt[(size_t)NDIM * KDIM];   // W^T : [N][K]

// ---------------- helpers ----------------
__device__ __forceinline__ uint32_t smem_u32(const void* p) {
    uint32_t a;
    asm("{ .reg .u64 t; cvta.to.shared.u64 t, %1; cvt.u32.u64 %0, t; }"
        : "=r"(a) : "l"(p));
    return a;
}
__device__ __forceinline__ float4 cvt_tf32x4(float4 v) {
    asm("cvt.rna.tf32.f32 %0, %0;" : "+f"(v.x));
    asm("cvt.rna.tf32.f32 %0, %0;" : "+f"(v.y));
    asm("cvt.rna.tf32.f32 %0, %0;" : "+f"(v.z));
    asm("cvt.rna.tf32.f32 %0, %0;" : "+f"(v.w));
    return v;
}
__device__ __forceinline__ void sts128(uint32_t addr, float4 v) {
    asm volatile("st.shared.v4.f32 [%0], {%1,%2,%3,%4};"
                 :: "r"(addr), "f"(v.x), "f"(v.y), "f"(v.z), "f"(v.w) : "memory");
}
__device__ __forceinline__ void ldsm4(uint32_t addr, uint32_t* r) {
    asm volatile("ldmatrix.sync.aligned.m8n8.x4.shared.b16 {%0,%1,%2,%3}, [%4];"
                 : "=r"(r[0]), "=r"(r[1]), "=r"(r[2]), "=r"(r[3]) : "r"(addr));
}
__device__ __forceinline__ void mma_tf32(float* c, const uint32_t* a,
                                         uint32_t b0, uint32_t b1) {
    asm volatile(
        "mma.sync.aligned.m16n8k8.row.col.f32.tf32.tf32.f32 "
        "{%0,%1,%2,%3}, {%4,%5,%6,%7}, {%8,%9}, {%0,%1,%2,%3};"
        : "+f"(c[0]), "+f"(c[1]), "+f"(c[2]), "+f"(c[3])
        : "r"(a[0]), "r"(a[1]), "r"(a[2]), "r"(a[3]), "r"(b0), "r"(b1));
}

// ---------------- W transpose (one small kernel, ~15us) ----------------
__global__ void transpose_W(const float* __restrict__ W) {
    __shared__ float t[32][33];
    const int n0 = blockIdx.x * 32, k0 = blockIdx.y * 32;
    const int tx = threadIdx.x, ty = threadIdx.y;
    #pragma unroll
    for (int j = 0; j < 4; ++j)
        t[ty + 8 * j][tx] = W[(size_t)(k0 + ty + 8 * j) * NDIM + n0 + tx];
    __syncthreads();
    #pragma unroll
    for (int j = 0; j < 4; ++j)
        g_Wt[(size_t)(n0 + ty + 8 * j) * KDIM + k0 + tx] = t[tx][ty + 8 * j];
}

// ---------------- main GEMM ----------------
__global__ __launch_bounds__(NTH, 1)
void ag_gemm_mma(const float* __restrict__ A,
                 const float* __restrict__ bias,
                 float* __restrict__ C)
{
    extern __shared__ char smem[];
    const uint32_t sb = smem_u32(smem);
    const int tid  = threadIdx.x;
    const int wid  = tid >> 5, lane = tid & 31;
    const int wm   = wid >> 2;          // 0..1 : warp m-half (64 rows)
    const int wn   = wid & 3;           // 0..3 : warp n-quarter (32 cols)
    const int m0   = blockIdx.y * BM;
    const int n0   = blockIdx.x * BN;

    // ldmatrix per-lane source coordinates (fixed; k8 varies by +32B).
    // A frag (m16k8): lanes 0-15 -> rows m+ (lane&15), k 0-3 ; lanes 16-31 -> k 4-7
    const uint32_t rowA  = (uint32_t)(wm * 64 + (lane & 15));
    const uint32_t kA16  = (uint32_t)((lane >> 4) * 16);
    // B frag pair (n16k8): lanes 0-7 n0-7/k0, 8-15 n0-7/k4, 16-23 n8-15/k0, 24-31 n8-15/k4
    const uint32_t rowB  = (uint32_t)(wn * 32 + (lane & 7) + ((lane >> 4) << 3));
    const uint32_t kB16  = (uint32_t)(((lane >> 3) & 1) * 16);

    float acc[4][4][4];                 // [m-tile][n-frag][4]
    #pragma unroll
    for (int i = 0; i < 4; ++i)
        #pragma unroll
        for (int j = 0; j < 4; ++j)
            #pragma unroll
            for (int q = 0; q < 4; ++q) acc[i][j][q] = 0.0f;

    // Global->reg prefetch buffers.
    float4 ar[4], br[4];
    const int grow = tid >> 3;          // 0..31 (row base, +32*i)
    const int gcol = tid & 7;           // 16B column group

    auto ldg_tile = [&](int kt) {
        const int k0 = kt * BK;
        const int r  = k0 >> 10;        // shard (BK=32 never crosses shards)
        const int kk = k0 & (KLOC - 1);
        const float* Ab = A + ((size_t)r * MDIM + m0 + grow) * KLOC + kk + gcol * 4;
        #pragma unroll
        for (int i = 0; i < 4; ++i)
            ar[i] = *reinterpret_cast<const float4*>(Ab + (size_t)i * 32 * KLOC);
        const float* Bb = g_Wt + (size_t)(n0 + grow) * KDIM + k0 + gcol * 4;
        #pragma unroll
        for (int i = 0; i < 4; ++i)
            br[i] = *reinterpret_cast<const float4*>(Bb + (size_t)i * 32 * KDIM);
    };

    auto sts_tile = [&](int s) {
        #pragma unroll
        for (int i = 0; i < 4; ++i) {
            uint32_t o = (uint32_t)(grow + 32 * i) * 128u + (uint32_t)gcol * 16u;
            sts128(sb + SM_A(s) + SWZ(o), cvt_tf32x4(ar[i]));
            sts128(sb + SM_B(s) + SWZ(o), cvt_tf32x4(br[i]));
        }
    };

    auto compute_tile = [&](int s) {
        #pragma unroll
        for (int k8 = 0; k8 < 4; ++k8) {
            uint32_t a[4][4], b[2][4];
            #pragma unroll
            for (int i = 0; i < 4; ++i) {
                uint32_t o = (rowA + 16u * i) * 128u + (uint32_t)k8 * 32u + kA16;
                ldsm4(sb + SM_A(s) + SWZ(o), a[i]);
            }
            #pragma unroll
            for (int j = 0; j < 2; ++j) {
                uint32_t o = (rowB + 16u * j) * 128u + (uint32_t)k8 * 32u + kB16;
                ldsm4(sb + SM_B(s) + SWZ(o), b[j]);
            }
            // b[j] = {b0(n8j), b1(n8j), b0(n8j+8), b1(n8j+8)}
            #pragma unroll
            for (int i = 0; i < 4; ++i) {
                #pragma unroll
                for (int jj = 0; jj < 4; ++jj)
                    mma_tf32(acc[i][jj], a[i],
                             b[jj >> 1][(jj & 1) * 2], b[jj >> 1][(jj & 1) * 2 + 1]);
            }
        }
    };

    // ---- pipeline: double-buffered smem, reg prefetch one tile ahead ----
    ldg_tile(0);
    sts_tile(0);
    ldg_tile(1);
    __syncthreads();

    for (int kt = 0; kt < NTILES; ++kt) {
        const int s = kt & 1;
        if (kt + 1 < NTILES) sts_tile(s ^ 1);   // regs hold tile kt+1
        if (kt + 2 < NTILES) ldg_tile(kt + 2);
        compute_tile(s);
        __syncthreads();
    }

    // ---- epilogue: fp32 accums -> +bias -> float2 stores ----
    const int er = lane >> 2;            // 0..7
    const int ec = (lane & 3) * 2;       // 0,2,4,6
    #pragma unroll
    for (int i = 0; i < 4; ++i) {
        const int gm = m0 + wm * 64 + i * 16 + er;
        #pragma unroll
        for (int jj = 0; jj < 4; ++jj) {
            const int gn = n0 + wn * 32 + jj * 8 + ec;
            const float bx = __ldg(bias + gn);
            const float by = __ldg(bias + gn + 1);
            float2 o0 = { acc[i][jj][0] + bx, acc[i][jj][1] + by };
            float2 o1 = { acc[i][jj][2] + bx, acc[i][jj][3] + by };
            *reinterpret_cast<float2*>(C + (size_t)gm * NDIM + gn) = o0;
            *reinterpret_cast<float2*>(C + (size_t)(gm + 8) * NDIM + gn) = o1;
        }
    }
}

extern "C" void kernel_launch(void* const* d_in, const int* in_sizes, int n_in,
                              void* d_out, int out_size)
{
    const float* all_act = (const float*)d_in[0];   // (8, 4096, 1024)
    const float* local_W = (const float*)d_in[1];   // (8192, 1024)
    const float* bias    = (const float*)d_in[2];   // (1024,)
    float* out = (float*)d_out;                     // (4096, 1024)

    // 1) transpose W -> g_Wt
    transpose_W<<<dim3(NDIM / 32, KDIM / 32), dim3(32, 8)>>>(local_W);

    // 2) mma.sync tf32 GEMM
    cudaFuncSetAttribute(ag_gemm_mma,
                         cudaFuncAttributeMaxDynamicSharedMemorySize, SMEM_TOTAL);
    dim3 grid(NDIM / BN, MDIM / BM);   // (8, 32) = 256 CTAs
    ag_gemm_mma<<<grid, NTH, SMEM_TOTAL>>>(all_act, bias, out);
}

// round 7
// speedup vs baseline: 3.7028x; 1.4900x over previous
#include <cuda_runtime.h>
#include <cstdint>
#include <cstddef>

// FusedAGGemm via mma.sync tf32 (HMMA), round 7.
//   C[M,N] = sum_r A_r[M,KLOC] @ W[r*KLOC:(r+1)*KLOC, N] + bias
// Prepass 1: A -> g_At (flat [M][K], all-gathered layout, cvt.rna tf32).
// Prepass 2: W -> g_Wt ([N][K] transpose, cvt.rna tf32).
// GEMM: 128x128 CTA tile, BK=32, SW128 smem, cp.async 3-stage pipeline,
//       2 CTAs/SM, ldmatrix.x4 feeds, m16n8k8 tf32 MMA, fp32 accumulators.

#define MDIM 4096
#define KLOC 1024
#define KDIM 8192
#define NDIM 1024

#define BM 128
#define BN 128
#define BK 32
#define NTH 256
#define NTILES (KDIM / BK)   // 256
#define NSTAGE 3

#define SWZ(o) ((o) ^ (((o) >> 3) & 0x70))
#define STAGE_BYTES 32768
#define SM_A(s) ((s) * STAGE_BYTES)
#define SM_B(s) ((s) * STAGE_BYTES + 16384)
#define SMEM_TOTAL (NSTAGE * STAGE_BYTES)   // 98304

__device__ float g_At[(size_t)MDIM * KDIM];   // 128 MB, tf32-rounded, gathered
__device__ float g_Wt[(size_t)NDIM * KDIM];   // 32 MB,  W^T tf32-rounded

// ---------------- helpers ----------------
__device__ __forceinline__ uint32_t smem_u32(const void* p) {
    uint32_t a;
    asm("{ .reg .u64 t; cvta.to.shared.u64 t, %1; cvt.u32.u64 %0, t; }"
        : "=r"(a) : "l"(p));
    return a;
}
__device__ __forceinline__ float4 cvt_tf32x4(float4 v) {
    asm("cvt.rna.tf32.f32 %0, %0;" : "+f"(v.x));
    asm("cvt.rna.tf32.f32 %0, %0;" : "+f"(v.y));
    asm("cvt.rna.tf32.f32 %0, %0;" : "+f"(v.z));
    asm("cvt.rna.tf32.f32 %0, %0;" : "+f"(v.w));
    return v;
}
__device__ __forceinline__ float cvt_tf32(float v) {
    asm("cvt.rna.tf32.f32 %0, %0;" : "+f"(v));
    return v;
}
__device__ __forceinline__ void cp_async16(uint32_t dst, const void* src) {
    asm volatile("cp.async.cg.shared.global [%0], [%1], 16;"
                 :: "r"(dst), "l"(src) : "memory");
}
__device__ __forceinline__ void ldsm4(uint32_t addr, uint32_t* r) {
    asm volatile("ldmatrix.sync.aligned.m8n8.x4.shared.b16 {%0,%1,%2,%3}, [%4];"
                 : "=r"(r[0]), "=r"(r[1]), "=r"(r[2]), "=r"(r[3]) : "r"(addr));
}
__device__ __forceinline__ void mma_tf32(float* c, const uint32_t* a,
                                         uint32_t b0, uint32_t b1) {
    asm volatile(
        "mma.sync.aligned.m16n8k8.row.col.f32.tf32.tf32.f32 "
        "{%0,%1,%2,%3}, {%4,%5,%6,%7}, {%8,%9}, {%0,%1,%2,%3};"
        : "+f"(c[0]), "+f"(c[1]), "+f"(c[2]), "+f"(c[3])
        : "r"(a[0]), "r"(a[1]), "r"(a[2]), "r"(a[3]), "r"(b0), "r"(b1));
}

// ---------------- prepass 1: A -> gathered flat tf32 ----------------
__global__ void prep_A(const float* __restrict__ A) {
    const size_t nf4 = (size_t)MDIM * KDIM / 4;   // 8M float4
    for (size_t i = (size_t)blockIdx.x * blockDim.x + threadIdx.x; i < nf4;
         i += (size_t)gridDim.x * blockDim.x) {
        size_t m = i >> 11;            // 2048 float4 per row
        size_t k = (i & 2047) << 2;
        size_t r = k >> 10, kk = k & (KLOC - 1);
        float4 v = *reinterpret_cast<const float4*>(
            A + ((r * MDIM + m) << 10) + kk);
        *reinterpret_cast<float4*>(&g_At[(m << 13) + k]) = cvt_tf32x4(v);
    }
}

// ---------------- prepass 2: W transpose + tf32 round ----------------
__global__ void prep_W(const float* __restrict__ W) {
    __shared__ float t[32][33];
    const int n0 = blockIdx.x * 32, k0 = blockIdx.y * 32;
    const int tx = threadIdx.x, ty = threadIdx.y;
    #pragma unroll
    for (int j = 0; j < 4; ++j)
        t[ty + 8 * j][tx] = W[(size_t)(k0 + ty + 8 * j) * NDIM + n0 + tx];
    __syncthreads();
    #pragma unroll
    for (int j = 0; j < 4; ++j)
        g_Wt[(size_t)(n0 + ty + 8 * j) * KDIM + k0 + tx] = cvt_tf32(t[tx][ty + 8 * j]);
}

// ---------------- main GEMM ----------------
__global__ __launch_bounds__(NTH, 2)
void ag_gemm_mma(const float* __restrict__ bias, float* __restrict__ C)
{
    extern __shared__ char smem[];
    const uint32_t sb = smem_u32(smem);
    const int tid  = threadIdx.x;
    const int wid  = tid >> 5, lane = tid & 31;
    const int wm   = wid >> 2;          // 0..1 : warp m-half (64 rows)
    const int wn   = wid & 3;           // 0..3 : warp n-quarter (32 cols)
    const int m0   = blockIdx.y * BM;
    const int n0   = blockIdx.x * BN;

    // ldmatrix per-lane coordinates (validated in R6).
    const uint32_t rowA = (uint32_t)(wm * 64 + (lane & 15));
    const uint32_t kA16 = (uint32_t)((lane >> 4) * 16);
    const uint32_t rowB = (uint32_t)(wn * 32 + (lane & 7) + ((lane >> 4) << 3));
    const uint32_t kB16 = (uint32_t)(((lane >> 3) & 1) * 16);

    float acc[4][4][4];
    #pragma unroll
    for (int i = 0; i < 4; ++i)
        #pragma unroll
        for (int j = 0; j < 4; ++j)
            #pragma unroll
            for (int q = 0; q < 4; ++q) acc[i][j][q] = 0.0f;

    // cp.async coordinates: 8 chunks of 16B per thread per tile.
    const int grow = tid >> 3;          // 0..31 (row base, +32*i)
    const int gcol = tid & 7;           // 16B col group

    auto issue_tile = [&](int kt, int s) {
        const float* Ab = g_At + (size_t)(m0 + grow) * KDIM + kt * BK + gcol * 4;
        const float* Bb = g_Wt + (size_t)(n0 + grow) * KDIM + kt * BK + gcol * 4;
        #pragma unroll
        for (int i = 0; i < 4; ++i) {
            uint32_t o = SWZ((uint32_t)(grow + 32 * i) * 128u + (uint32_t)gcol * 16u);
            cp_async16(sb + SM_A(s) + o, Ab + (size_t)i * 32 * KDIM);
            cp_async16(sb + SM_B(s) + o, Bb + (size_t)i * 32 * KDIM);
        }
        asm volatile("cp.async.commit_group;" ::: "memory");
    };

    auto compute_tile = [&](int s) {
        #pragma unroll
        for (int k8 = 0; k8 < 4; ++k8) {
            uint32_t a[4][4], b[2][4];
            #pragma unroll
            for (int i = 0; i < 4; ++i) {
                uint32_t o = (rowA + 16u * i) * 128u + (uint32_t)k8 * 32u + kA16;
                ldsm4(sb + SM_A(s) + SWZ(o), a[i]);
            }
            #pragma unroll
            for (int j = 0; j < 2; ++j) {
                uint32_t o = (rowB + 16u * j) * 128u + (uint32_t)k8 * 32u + kB16;
                ldsm4(sb + SM_B(s) + SWZ(o), b[j]);
            }
            #pragma unroll
            for (int i = 0; i < 4; ++i) {
                #pragma unroll
                for (int jj = 0; jj < 4; ++jj)
                    mma_tf32(acc[i][jj], a[i],
                             b[jj >> 1][(jj & 1) * 2], b[jj >> 1][(jj & 1) * 2 + 1]);
            }
        }
    };

    // ---- 3-stage cp.async pipeline ----
    issue_tile(0, 0);
    issue_tile(1, 1);

    for (int kt = 0; kt < NTILES; ++kt) {
        const int s = kt % NSTAGE;
        asm volatile("cp.async.wait_group 1;" ::: "memory");   // tile kt landed
        __syncthreads();                                       // prev compute done
        if (kt + 2 < NTILES) issue_tile(kt + 2, (kt + 2) % NSTAGE);
        compute_tile(s);
    }

    // ---- epilogue: +bias, float2 stores ----
    const int er = lane >> 2;
    const int ec = (lane & 3) * 2;
    #pragma unroll
    for (int i = 0; i < 4; ++i) {
        const int gm = m0 + wm * 64 + i * 16 + er;
        #pragma unroll
        for (int jj = 0; jj < 4; ++jj) {
            const int gn = n0 + wn * 32 + jj * 8 + ec;
            const float bx = __ldg(bias + gn);
            const float by = __ldg(bias + gn + 1);
            float2 o0 = { acc[i][jj][0] + bx, acc[i][jj][1] + by };
            float2 o1 = { acc[i][jj][2] + bx, acc[i][jj][3] + by };
            *reinterpret_cast<float2*>(C + (size_t)gm * NDIM + gn) = o0;
            *reinterpret_cast<float2*>(C + (size_t)(gm + 8) * NDIM + gn) = o1;
        }
    }
}

extern "C" void kernel_launch(void* const* d_in, const int* in_sizes, int n_in,
                              void* d_out, int out_size)
{
    const float* all_act = (const float*)d_in[0];   // (8, 4096, 1024)
    const float* local_W = (const float*)d_in[1];   // (8192, 1024)
    const float* bias    = (const float*)d_in[2];   // (1024,)
    float* out = (float*)d_out;                     // (4096, 1024)

    prep_A<<<2048, 256>>>(all_act);
    prep_W<<<dim3(NDIM / 32, KDIM / 32), dim3(32, 8)>>>(local_W);

    cudaFuncSetAttribute(ag_gemm_mma,
                         cudaFuncAttributeMaxDynamicSharedMemorySize, SMEM_TOTAL);
    dim3 grid(NDIM / BN, MDIM / BM);   // (8, 32) = 256 CTAs
    ag_gemm_mma<<<grid, NTH, SMEM_TOTAL>>>(bias, out);
}